// round 6
// baseline (speedup 1.0000x reference)
#include <cuda_runtime.h>
#include <cuda_fp16.h>
#include <cstdint>

#define R_TOT   48
#define N_NODES 1000
#define RN      48000          // R_TOT * N_NODES
#define E_IN    12000
#define F_DIM   64
#define HC      256            // H * C
#define H_HEADS 4
#define E_MAX   (E_IN + N_NODES)

// ---------------- scratch (static device globals; no allocation) -------------
// h stored as fp16: [RN][32] uint4, each uint4 = 8 halves (16B), lane l owns uint4 #l
__device__ uint4 g_hv[(size_t)RN * 32];
__device__ float g_asrc[RN * H_HEADS];
__device__ float g_adst[RN * H_HEADS];
__device__ int   g_cnt[N_NODES];        // zero-init (BSS); re-zeroed by k_scatter
__device__ int   g_rowptr[N_NODES + 1];
__device__ int   g_cursor[N_NODES];
__device__ int   g_csrc[E_MAX];
__device__ int   g_is32;

// ---------------- packed fp32x2 FMA (sm_100+) --------------------------------
union F2U { unsigned long long u; float2 f; };
__device__ __forceinline__ unsigned long long fma2(unsigned long long a,
                                                   unsigned long long b,
                                                   unsigned long long c) {
    unsigned long long d;
    asm("fma.rn.f32x2 %0, %1, %2, %3;" : "=l"(d) : "l"(a), "l"(b), "l"(c));
    return d;
}

// ---------------- CSR build: 3 multi-SM micro-kernels -------------------------
// Original self-loops dropped (reference masks them to -inf => exp == 0 exactly);
// one added self-loop per node occupies the first CSR slot deterministically.

// Width detect by sampling: if edge_index is int64 (values < 1000), EVERY odd
// 32-bit word is zero. 32 sampled odd words all zero on int32 random data has
// probability ~1e-96. Sampled positions stay within the first 24000 words.
__device__ __forceinline__ int detect_is32_warp(const int* e32, int lane) {
    int f = (e32[2 * (lane * 375) + 1] != 0);
    unsigned b = __ballot_sync(0xffffffffu, f);
    return b != 0;
}

__global__ __launch_bounds__(256) void k_count(const void* __restrict__ ei) {
    __shared__ int s_is32;
    const int* e32 = (const int*)ei;
    const long long* e64 = (const long long*)ei;
    int t = threadIdx.x;
    if (t < 32) {
        int is32 = detect_is32_warp(e32, t);
        if (t == 0) {
            s_is32 = is32;
            if (blockIdx.x == 0) g_is32 = is32;
        }
    }
    __syncthreads();
    int is32 = s_is32;
    int e = blockIdx.x * 256 + t;
    if (e < E_IN) {
        int s = is32 ? e32[e] : (int)e64[e];
        int d = is32 ? e32[E_IN + e] : (int)e64[E_IN + e];
        if (s != d) atomicAdd(&g_cnt[d], 1);   // spread over 1000 L2 addresses
    }
}

__global__ __launch_bounds__(1024) void k_scan() {   // one block
    __shared__ int s_wsum[32];
    int t = threadIdx.x, lane = t & 31, wid = t >> 5;
    int v = (t < N_NODES) ? (g_cnt[t] + 1) : 0;      // +1 = added self-loop
    int x = v;
#pragma unroll
    for (int o = 1; o < 32; o <<= 1) {
        int y = __shfl_up_sync(0xffffffffu, x, o);
        if (lane >= o) x += y;
    }
    if (lane == 31) s_wsum[wid] = x;
    __syncthreads();
    if (wid == 0) {
        int w = s_wsum[lane];
#pragma unroll
        for (int o = 1; o < 32; o <<= 1) {
            int y = __shfl_up_sync(0xffffffffu, w, o);
            if (lane >= o) w += y;
        }
        s_wsum[lane] = w;
    }
    __syncthreads();
    int incl = x + (wid ? s_wsum[wid - 1] : 0);
    int excl = incl - v;
    if (t < N_NODES) {
        g_rowptr[t] = excl;
        g_csrc[excl] = t;                // self-loop first, deterministic
        g_cursor[t] = excl + 1;
    }
    if (t == N_NODES - 1) g_rowptr[N_NODES] = incl;
}

__global__ __launch_bounds__(256) void k_scatter(const void* __restrict__ ei) {
    const int* e32 = (const int*)ei;
    const long long* e64 = (const long long*)ei;
    int t = threadIdx.x;
    int e = blockIdx.x * 256 + t;
    int is32 = g_is32;
    if (e < E_IN) {
        int s = is32 ? e32[e] : (int)e64[e];
        int d = is32 ? e32[E_IN + e] : (int)e64[E_IN + e];
        if (s != d) {
            int p = atomicAdd(&g_cursor[d], 1);
            g_csrc[p] = s;
        }
    }
    if (e < N_NODES) g_cnt[e] = 0;       // reset for next graph replay
}

// ---------------- projection GEMM + attention logits --------------------------
// Block: 256 threads = 8 warps; block tile = 32 rows x 256 cols, K=64.
// Warp: 4 rows (acc = 32 u64 regs, no spills at 2 blocks/SM).
// Lane l: cols [8l,8l+8) (one head per lane).
// K chunked by 4: stage 4 W rows in regs (8 LDG.128), x via LDS.128 broadcast.
__global__ __launch_bounds__(256, 2) void k_gemm(const float* __restrict__ x,
                                                 const float* __restrict__ W,
                                                 const float* __restrict__ attS,
                                                 const float* __restrict__ attD) {
    __shared__ float sX[32][72];          // 72 floats/row keeps float4 alignment
    __shared__ float sAS[HC], sAD[HC];

    int t = threadIdx.x, warp = t >> 5, lane = t & 31;
    int rowBase = blockIdx.x * 32;

    for (int i = t; i < 32 * 16; i += 256) {
        int rr = i >> 4, j = i & 15;
        float4 v = ((const float4*)(x + (size_t)(rowBase + rr) * F_DIM))[j];
        *(float4*)&sX[rr][j * 4] = v;
    }
    if (t < HC) { sAS[t] = attS[t]; sAD[t] = attD[t]; }
    __syncthreads();

    int c0 = lane * 8;
    unsigned long long acc[4][4];
#pragma unroll
    for (int rr = 0; rr < 4; rr++)
#pragma unroll
        for (int j = 0; j < 4; j++) acc[rr][j] = 0ULL;

    const float4* wbase = (const float4*)(W + c0);   // row stride 64 float4

#pragma unroll 4
    for (int f4 = 0; f4 < F_DIM; f4 += 4) {
        // stage W rows f4..f4+3 (8 x LDG.128, L1-resident)
        F2U wb[4][4];
#pragma unroll
        for (int j = 0; j < 4; j++) {
            float4 wa = wbase[(f4 + j) * 64];
            float4 wc = wbase[(f4 + j) * 64 + 1];
            wb[j][0].f = make_float2(wa.x, wa.y);
            wb[j][1].f = make_float2(wa.z, wa.w);
            wb[j][2].f = make_float2(wc.x, wc.y);
            wb[j][3].f = make_float2(wc.z, wc.w);
        }
#pragma unroll
        for (int rr = 0; rr < 4; rr++) {
            float4 xv = *(const float4*)&sX[warp * 4 + rr][f4];  // broadcast LDS.128
            float xs[4] = {xv.x, xv.y, xv.z, xv.w};
#pragma unroll
            for (int j = 0; j < 4; j++) {
                F2U xb; xb.f = make_float2(xs[j], xs[j]);
                acc[rr][0] = fma2(xb.u, wb[j][0].u, acc[rr][0]);
                acc[rr][1] = fma2(xb.u, wb[j][1].u, acc[rr][1]);
                acc[rr][2] = fma2(xb.u, wb[j][2].u, acc[rr][2]);
                acc[rr][3] = fma2(xb.u, wb[j][3].u, acc[rr][3]);
            }
        }
    }

    int head = c0 >> 6;
#pragma unroll
    for (int rr = 0; rr < 4; rr++) {
        int row = rowBase + warp * 4 + rr;
        float a[8];
#pragma unroll
        for (int j = 0; j < 4; j++) {
            F2U u; u.u = acc[rr][j];
            a[2 * j] = u.f.x; a[2 * j + 1] = u.f.y;
        }
        float as = 0.f, ad = 0.f;
#pragma unroll
        for (int k = 0; k < 8; k++) {
            as += a[k] * sAS[c0 + k];
            ad += a[k] * sAD[c0 + k];
        }
#pragma unroll
        for (int off = 1; off < 8; off <<= 1) {
            as += __shfl_xor_sync(0xffffffffu, as, off);
            ad += __shfl_xor_sync(0xffffffffu, ad, off);
        }
        if ((lane & 7) == 0) {
            g_asrc[row * 4 + head] = as;
            g_adst[row * 4 + head] = ad;
        }
        __half2 p0 = __floats2half2_rn(a[0], a[1]);
        __half2 p1 = __floats2half2_rn(a[2], a[3]);
        __half2 p2 = __floats2half2_rn(a[4], a[5]);
        __half2 p3 = __floats2half2_rn(a[6], a[7]);
        uint4 u;
        u.x = *reinterpret_cast<unsigned*>(&p0);
        u.y = *reinterpret_cast<unsigned*>(&p1);
        u.z = *reinterpret_cast<unsigned*>(&p2);
        u.w = *reinterpret_cast<unsigned*>(&p3);
        g_hv[(size_t)row * 32 + lane] = u;
    }
}

// ---------------- softmax aggregation (single pass, one warp per (r, dst)) ----
// No max-shift: logits bounded far below 80, so exp(e) equals the reference's
// shifted softmax; den eps 1e-16 matches ref.
__global__ __launch_bounds__(256) void k_agg(const float* __restrict__ bias,
                                             float* __restrict__ out) {
    int gw = (blockIdx.x * blockDim.x + threadIdx.x) >> 5;
    int lane = threadIdx.x & 31;
    if (gw >= RN) return;
    int r = gw / N_NODES, i = gw - r * N_NODES;
    int head = lane >> 3;
    int start = g_rowptr[i], end = g_rowptr[i + 1];
    int rbase = r * N_NODES;

    float adsth = g_adst[(rbase + i) * 4 + head];

    float den = 1e-16f;
    float a0 = 0.f, a1 = 0.f, a2 = 0.f, a3 = 0.f;
    float a4 = 0.f, a5 = 0.f, a6 = 0.f, a7 = 0.f;

#pragma unroll 2
    for (int k = start; k < end; k++) {
        int s = g_csrc[k];
        float e = g_asrc[(rbase + s) * 4 + head] + adsth;
        e = (e > 0.f) ? e : 0.2f * e;
        float w = __expf(fminf(e, 80.f));
        den += w;
        uint4 u = g_hv[(size_t)(rbase + s) * 32 + lane];   // 16B/lane, 512B/warp
        float2 f0 = __half22float2(*reinterpret_cast<__half2*>(&u.x));
        float2 f1 = __half22float2(*reinterpret_cast<__half2*>(&u.y));
        float2 f2 = __half22float2(*reinterpret_cast<__half2*>(&u.z));
        float2 f3 = __half22float2(*reinterpret_cast<__half2*>(&u.w));
        a0 += w * f0.x; a1 += w * f0.y; a2 += w * f1.x; a3 += w * f1.y;
        a4 += w * f2.x; a5 += w * f2.y; a6 += w * f3.x; a7 += w * f3.y;
    }

    float inv = 1.0f / den;
    float a[8] = {a0 * inv, a1 * inv, a2 * inv, a3 * inv,
                  a4 * inv, a5 * inv, a6 * inv, a7 * inv};

    // head mean: lanes l, l^8, l^16, l^24 hold same channel, different heads
#pragma unroll
    for (int k = 0; k < 8; k++) {
        a[k] += __shfl_xor_sync(0xffffffffu, a[k], 8);
        a[k] += __shfl_xor_sync(0xffffffffu, a[k], 16);
    }

    if (lane < 8) {
        const float4* bp = (const float4*)bias;
        float4 b0 = bp[lane * 2], b1 = bp[lane * 2 + 1];
        float4 o0 = make_float4(0.25f * a[0] + b0.x, 0.25f * a[1] + b0.y,
                                0.25f * a[2] + b0.z, 0.25f * a[3] + b0.w);
        float4 o1 = make_float4(0.25f * a[4] + b1.x, 0.25f * a[5] + b1.y,
                                0.25f * a[6] + b1.z, 0.25f * a[7] + b1.w);
        float4* op = (float4*)(out + (size_t)(rbase + i) * 64 + lane * 8);
        op[0] = o0;
        op[1] = o1;
    }
}

// ---------------- launch ------------------------------------------------------
extern "C" void kernel_launch(void* const* d_in, const int* in_sizes, int n_in,
                              void* d_out, int out_size) {
    const float* x    = (const float*)d_in[0];
    const void*  ei   = d_in[1];
    const float* W    = (const float*)d_in[2];
    const float* attS = (const float*)d_in[3];
    const float* attD = (const float*)d_in[4];
    const float* bias = (const float*)d_in[5];
    float* out = (float*)d_out;

    k_count<<<(E_IN + 255) / 256, 256>>>(ei);
    k_scan<<<1, 1024>>>();
    k_scatter<<<(E_IN + 255) / 256, 256>>>(ei);
    k_gemm<<<RN / 32, 256>>>(x, W, attS, attD);
    k_agg<<<RN / 8, 256>>>(bias, out);
}

// round 7
// speedup vs baseline: 1.1992x; 1.1992x over previous
#include <cuda_runtime.h>
#include <cuda_fp16.h>
#include <cstdint>

#define R_TOT   48
#define N_NODES 1000
#define RN      48000          // R_TOT * N_NODES
#define E_IN    12000
#define F_DIM   64
#define HC      256            // H * C
#define H_HEADS 4
#define E_MAX   (E_IN + N_NODES)

// ---------------- scratch (static device globals; no allocation) -------------
// h stored as fp16: [RN][32] uint4 (= [RN][64] uint2), lane-granular 16B/8B chunks
__device__ uint4 g_hv[(size_t)RN * 32];
__device__ float g_asrc[RN * H_HEADS];
__device__ float g_adst[RN * H_HEADS];
__device__ int   g_cnt[N_NODES];        // zero-init (BSS); re-zeroed by k_scatter
__device__ int   g_rowptr[N_NODES + 1];
__device__ int   g_cursor[N_NODES];
__device__ int   g_csrc[E_MAX];
__device__ int   g_is32;

// ---------------- packed fp32x2 FMA (sm_100+) --------------------------------
union F2U { unsigned long long u; float2 f; };
__device__ __forceinline__ unsigned long long fma2(unsigned long long a,
                                                   unsigned long long b,
                                                   unsigned long long c) {
    unsigned long long d;
    asm("fma.rn.f32x2 %0, %1, %2, %3;" : "=l"(d) : "l"(a), "l"(b), "l"(c));
    return d;
}

// ---------------- CSR build: 3 multi-SM micro-kernels -------------------------
// Original self-loops dropped (reference masks them to -inf => exp == 0 exactly);
// one added self-loop per node occupies the first CSR slot deterministically.

// Width detect by sampling: if edge_index is int64 (values < 1000), EVERY odd
// 32-bit word is zero. 32 sampled odd words all zero on int32 random data has
// probability ~1e-96. Sampled positions stay within the first 24000 words.
__device__ __forceinline__ int detect_is32_warp(const int* e32, int lane) {
    int f = (e32[2 * (lane * 375) + 1] != 0);
    unsigned b = __ballot_sync(0xffffffffu, f);
    return b != 0;
}

__global__ __launch_bounds__(256) void k_count(const void* __restrict__ ei) {
    __shared__ int s_is32;
    const int* e32 = (const int*)ei;
    const long long* e64 = (const long long*)ei;
    int t = threadIdx.x;
    if (t < 32) {
        int is32 = detect_is32_warp(e32, t);
        if (t == 0) {
            s_is32 = is32;
            if (blockIdx.x == 0) g_is32 = is32;
        }
    }
    __syncthreads();
    int is32 = s_is32;
    int e = blockIdx.x * 256 + t;
    if (e < E_IN) {
        int s = is32 ? e32[e] : (int)e64[e];
        int d = is32 ? e32[E_IN + e] : (int)e64[E_IN + e];
        if (s != d) atomicAdd(&g_cnt[d], 1);   // spread over 1000 L2 addresses
    }
}

__global__ __launch_bounds__(1024) void k_scan() {   // one block
    __shared__ int s_wsum[32];
    int t = threadIdx.x, lane = t & 31, wid = t >> 5;
    int v = (t < N_NODES) ? (g_cnt[t] + 1) : 0;      // +1 = added self-loop
    int x = v;
#pragma unroll
    for (int o = 1; o < 32; o <<= 1) {
        int y = __shfl_up_sync(0xffffffffu, x, o);
        if (lane >= o) x += y;
    }
    if (lane == 31) s_wsum[wid] = x;
    __syncthreads();
    if (wid == 0) {
        int w = s_wsum[lane];
#pragma unroll
        for (int o = 1; o < 32; o <<= 1) {
            int y = __shfl_up_sync(0xffffffffu, w, o);
            if (lane >= o) w += y;
        }
        s_wsum[lane] = w;
    }
    __syncthreads();
    int incl = x + (wid ? s_wsum[wid - 1] : 0);
    int excl = incl - v;
    if (t < N_NODES) {
        g_rowptr[t] = excl;
        g_csrc[excl] = t;                // self-loop first, deterministic
        g_cursor[t] = excl + 1;
    }
    if (t == N_NODES - 1) g_rowptr[N_NODES] = incl;
}

__global__ __launch_bounds__(256) void k_scatter(const void* __restrict__ ei) {
    const int* e32 = (const int*)ei;
    const long long* e64 = (const long long*)ei;
    int t = threadIdx.x;
    int e = blockIdx.x * 256 + t;
    int is32 = g_is32;
    if (e < E_IN) {
        int s = is32 ? e32[e] : (int)e64[e];
        int d = is32 ? e32[E_IN + e] : (int)e64[E_IN + e];
        if (s != d) {
            int p = atomicAdd(&g_cursor[d], 1);
            g_csrc[p] = s;
        }
    }
    if (e < N_NODES) g_cnt[e] = 0;       // reset for next graph replay
}

// ---------------- projection GEMM + attention logits --------------------------
// Block: 256 threads = 8 warps; block tile = 64 rows x 256 cols, K = 64.
// Warp tile: 16 rows x 128 cols. warp>>1 picks the 16-row group, warp&1 picks
// the 128-col half. Lane owns 4 columns: one LDG.128 of W covers lane's 4 cols
// for 4 K-rows (W traffic amortized over 16 output rows -> L1 ~12% of fma time).
__global__ __launch_bounds__(256, 2) void k_gemm(const float* __restrict__ x,
                                                 const float* __restrict__ W,
                                                 const float* __restrict__ attS,
                                                 const float* __restrict__ attD) {
    __shared__ float sX[64][72];          // float4-aligned rows
    __shared__ float sAS[HC], sAD[HC];

    int t = threadIdx.x, warp = t >> 5, lane = t & 31;
    int rowBase = blockIdx.x * 64;
    int rowG = (warp >> 1) * 16;                    // 16-row group within block
    int c0 = (warp & 1) * 128 + lane * 4;           // 4 owned columns

    for (int i = t; i < 64 * 16; i += 256) {
        int rr = i >> 4, j = i & 15;
        float4 v = ((const float4*)(x + (size_t)(rowBase + rr) * F_DIM))[j];
        *(float4*)&sX[rr][j * 4] = v;
    }
    if (t < HC) { sAS[t] = attS[t]; sAD[t] = attD[t]; }
    __syncthreads();

    unsigned long long acc[16][2];
#pragma unroll
    for (int rr = 0; rr < 16; rr++) { acc[rr][0] = 0ULL; acc[rr][1] = 0ULL; }

#pragma unroll 4
    for (int f4 = 0; f4 < F_DIM; f4 += 4) {
        // stage W[f4..f4+3][c0..c0+3]: 4 x LDG.128 (L1-resident)
        F2U wb[4][2];
#pragma unroll
        for (int j = 0; j < 4; j++) {
            float4 wv = *(const float4*)(W + (size_t)(f4 + j) * HC + c0);
            wb[j][0].f = make_float2(wv.x, wv.y);
            wb[j][1].f = make_float2(wv.z, wv.w);
        }
#pragma unroll
        for (int rr = 0; rr < 16; rr++) {
            float4 xv = *(const float4*)&sX[rowG + rr][f4];  // broadcast LDS.128
            F2U xb0; xb0.f = make_float2(xv.x, xv.x);
            F2U xb1; xb1.f = make_float2(xv.y, xv.y);
            F2U xb2; xb2.f = make_float2(xv.z, xv.z);
            F2U xb3; xb3.f = make_float2(xv.w, xv.w);
            acc[rr][0] = fma2(xb0.u, wb[0][0].u, acc[rr][0]);
            acc[rr][1] = fma2(xb0.u, wb[0][1].u, acc[rr][1]);
            acc[rr][0] = fma2(xb1.u, wb[1][0].u, acc[rr][0]);
            acc[rr][1] = fma2(xb1.u, wb[1][1].u, acc[rr][1]);
            acc[rr][0] = fma2(xb2.u, wb[2][0].u, acc[rr][0]);
            acc[rr][1] = fma2(xb2.u, wb[2][1].u, acc[rr][1]);
            acc[rr][0] = fma2(xb3.u, wb[3][0].u, acc[rr][0]);
            acc[rr][1] = fma2(xb3.u, wb[3][1].u, acc[rr][1]);
        }
    }

    int head = c0 >> 6;                  // 16 consecutive lanes share a head
#pragma unroll
    for (int rr = 0; rr < 16; rr++) {
        int row = rowBase + rowG + rr;
        F2U u0, u1; u0.u = acc[rr][0]; u1.u = acc[rr][1];
        float a0 = u0.f.x, a1 = u0.f.y, a2 = u1.f.x, a3 = u1.f.y;

        float as = a0 * sAS[c0] + a1 * sAS[c0 + 1] + a2 * sAS[c0 + 2] + a3 * sAS[c0 + 3];
        float ad = a0 * sAD[c0] + a1 * sAD[c0 + 1] + a2 * sAD[c0 + 2] + a3 * sAD[c0 + 3];
#pragma unroll
        for (int off = 1; off < 16; off <<= 1) {
            as += __shfl_xor_sync(0xffffffffu, as, off);
            ad += __shfl_xor_sync(0xffffffffu, ad, off);
        }
        if ((lane & 15) == 0) {
            g_asrc[row * 4 + head] = as;
            g_adst[row * 4 + head] = ad;
        }
        __half2 p0 = __floats2half2_rn(a0, a1);
        __half2 p1 = __floats2half2_rn(a2, a3);
        uint2 uo;
        uo.x = *reinterpret_cast<unsigned*>(&p0);
        uo.y = *reinterpret_cast<unsigned*>(&p1);
        ((uint2*)g_hv)[(size_t)row * 64 + (c0 >> 2)] = uo;
    }
}

// ---------------- softmax aggregation (single pass, one warp per (r, dst)) ----
// No max-shift: logits bounded far below 80, so exp(e) equals the reference's
// shifted softmax; den eps 1e-16 matches ref.
__global__ __launch_bounds__(256) void k_agg(const float* __restrict__ bias,
                                             float* __restrict__ out) {
    int gw = (blockIdx.x * blockDim.x + threadIdx.x) >> 5;
    int lane = threadIdx.x & 31;
    if (gw >= RN) return;
    int r = gw / N_NODES, i = gw - r * N_NODES;
    int head = lane >> 3;
    int start = g_rowptr[i], end = g_rowptr[i + 1];
    int rbase = r * N_NODES;

    float adsth = g_adst[(rbase + i) * 4 + head];

    float den = 1e-16f;
    float a0 = 0.f, a1 = 0.f, a2 = 0.f, a3 = 0.f;
    float a4 = 0.f, a5 = 0.f, a6 = 0.f, a7 = 0.f;

#pragma unroll 2
    for (int k = start; k < end; k++) {
        int s = g_csrc[k];
        float e = g_asrc[(rbase + s) * 4 + head] + adsth;
        e = (e > 0.f) ? e : 0.2f * e;
        float w = __expf(fminf(e, 80.f));
        den += w;
        uint4 u = g_hv[(size_t)(rbase + s) * 32 + lane];   // 16B/lane, 512B/warp
        float2 f0 = __half22float2(*reinterpret_cast<__half2*>(&u.x));
        float2 f1 = __half22float2(*reinterpret_cast<__half2*>(&u.y));
        float2 f2 = __half22float2(*reinterpret_cast<__half2*>(&u.z));
        float2 f3 = __half22float2(*reinterpret_cast<__half2*>(&u.w));
        a0 += w * f0.x; a1 += w * f0.y; a2 += w * f1.x; a3 += w * f1.y;
        a4 += w * f2.x; a5 += w * f2.y; a6 += w * f3.x; a7 += w * f3.y;
    }

    float inv = 1.0f / den;
    float a[8] = {a0 * inv, a1 * inv, a2 * inv, a3 * inv,
                  a4 * inv, a5 * inv, a6 * inv, a7 * inv};

    // head mean: lanes l, l^8, l^16, l^24 hold same channel, different heads
#pragma unroll
    for (int k = 0; k < 8; k++) {
        a[k] += __shfl_xor_sync(0xffffffffu, a[k], 8);
        a[k] += __shfl_xor_sync(0xffffffffu, a[k], 16);
    }

    if (lane < 8) {
        const float4* bp = (const float4*)bias;
        float4 b0 = bp[lane * 2], b1 = bp[lane * 2 + 1];
        float4 o0 = make_float4(0.25f * a[0] + b0.x, 0.25f * a[1] + b0.y,
                                0.25f * a[2] + b0.z, 0.25f * a[3] + b0.w);
        float4 o1 = make_float4(0.25f * a[4] + b1.x, 0.25f * a[5] + b1.y,
                                0.25f * a[6] + b1.z, 0.25f * a[7] + b1.w);
        float4* op = (float4*)(out + (size_t)(rbase + i) * 64 + lane * 8);
        op[0] = o0;
        op[1] = o1;
    }
}

// ---------------- launch ------------------------------------------------------
extern "C" void kernel_launch(void* const* d_in, const int* in_sizes, int n_in,
                              void* d_out, int out_size) {
    const float* x    = (const float*)d_in[0];
    const void*  ei   = d_in[1];
    const float* W    = (const float*)d_in[2];
    const float* attS = (const float*)d_in[3];
    const float* attD = (const float*)d_in[4];
    const float* bias = (const float*)d_in[5];
    float* out = (float*)d_out;

    k_count<<<(E_IN + 255) / 256, 256>>>(ei);
    k_scan<<<1, 1024>>>();
    k_scatter<<<(E_IN + 255) / 256, 256>>>(ei);
    k_gemm<<<RN / 64, 256>>>(x, W, attS, attD);
    k_agg<<<RN / 8, 256>>>(bias, out);
}

// round 8
// speedup vs baseline: 1.2555x; 1.0469x over previous
#include <cuda_runtime.h>
#include <cuda_fp16.h>
#include <cstdint>

#define R_TOT   48
#define N_NODES 1000
#define RN      48000          // R_TOT * N_NODES
#define E_IN    12000
#define F_DIM   64
#define HC      256            // H * C
#define H_HEADS 4
#define E_MAX   (E_IN + N_NODES)

// ---------------- scratch (static device globals; no allocation) -------------
// h stored as fp16, row-major [RN][256] halves (viewed as [RN][32] uint4 by k_agg)
__device__ uint4  g_hv[(size_t)RN * 32];
__device__ float  g_asrc[RN * H_HEADS];
__device__ float  g_adst[RN * H_HEADS];
__device__ float4 g_Wf[8 * 32 * 32];    // pre-split W fragments: [kstep][ntile][lane]
__device__ int    g_cnt[N_NODES];       // zero-init (BSS); re-zeroed by k_scatter
__device__ int    g_rowptr[N_NODES + 1];
__device__ int    g_cursor[N_NODES];
__device__ int    g_csrc[E_MAX];
__device__ int    g_is32;

// ---------------- tf32 helpers ------------------------------------------------
__device__ __forceinline__ unsigned tf32_rna(float v) {
    unsigned r;
    asm("cvt.rna.tf32.f32 %0, %1;" : "=r"(r) : "f"(v));
    return r;
}

#define MMA_TF32(d, a, b0, b1)                                                  \
    asm volatile("mma.sync.aligned.m16n8k8.row.col.f32.tf32.tf32.f32 "          \
                 "{%0,%1,%2,%3}, {%4,%5,%6,%7}, {%8,%9}, {%0,%1,%2,%3};"        \
                 : "+f"((d)[0]), "+f"((d)[1]), "+f"((d)[2]), "+f"((d)[3])       \
                 : "r"((a)[0]), "r"((a)[1]), "r"((a)[2]), "r"((a)[3]),          \
                   "r"(b0), "r"(b1))

// ---------------- CSR build: 3 multi-SM micro-kernels -------------------------
// Original self-loops dropped (reference masks them to -inf => exp == 0 exactly);
// one added self-loop per node occupies the first CSR slot deterministically.

// Width detect by sampling: if edge_index is int64 (values < 1000), EVERY odd
// 32-bit word is zero. 32 sampled odd words all zero on int32 random data has
// probability ~1e-96. Sampled positions stay within the first 24000 words.
__device__ __forceinline__ int detect_is32_warp(const int* e32, int lane) {
    int f = (e32[2 * (lane * 375) + 1] != 0);
    unsigned b = __ballot_sync(0xffffffffu, f);
    return b != 0;
}

__global__ __launch_bounds__(256) void k_count(const void* __restrict__ ei) {
    __shared__ int s_is32;
    const int* e32 = (const int*)ei;
    const long long* e64 = (const long long*)ei;
    int t = threadIdx.x;
    if (t < 32) {
        int is32 = detect_is32_warp(e32, t);
        if (t == 0) {
            s_is32 = is32;
            if (blockIdx.x == 0) g_is32 = is32;
        }
    }
    __syncthreads();
    int is32 = s_is32;
    int e = blockIdx.x * 256 + t;
    if (e < E_IN) {
        int s = is32 ? e32[e] : (int)e64[e];
        int d = is32 ? e32[E_IN + e] : (int)e64[E_IN + e];
        if (s != d) atomicAdd(&g_cnt[d], 1);   // spread over 1000 L2 addresses
    }
}

__global__ __launch_bounds__(1024) void k_scan() {   // one block
    __shared__ int s_wsum[32];
    int t = threadIdx.x, lane = t & 31, wid = t >> 5;
    int v = (t < N_NODES) ? (g_cnt[t] + 1) : 0;      // +1 = added self-loop
    int x = v;
#pragma unroll
    for (int o = 1; o < 32; o <<= 1) {
        int y = __shfl_up_sync(0xffffffffu, x, o);
        if (lane >= o) x += y;
    }
    if (lane == 31) s_wsum[wid] = x;
    __syncthreads();
    if (wid == 0) {
        int w = s_wsum[lane];
#pragma unroll
        for (int o = 1; o < 32; o <<= 1) {
            int y = __shfl_up_sync(0xffffffffu, w, o);
            if (lane >= o) w += y;
        }
        s_wsum[lane] = w;
    }
    __syncthreads();
    int incl = x + (wid ? s_wsum[wid - 1] : 0);
    int excl = incl - v;
    if (t < N_NODES) {
        g_rowptr[t] = excl;
        g_csrc[excl] = t;                // self-loop first, deterministic
        g_cursor[t] = excl + 1;
    }
    if (t == N_NODES - 1) g_rowptr[N_NODES] = incl;
}

__global__ __launch_bounds__(256) void k_scatter(const void* __restrict__ ei) {
    const int* e32 = (const int*)ei;
    const long long* e64 = (const long long*)ei;
    int t = threadIdx.x;
    int e = blockIdx.x * 256 + t;
    int is32 = g_is32;
    if (e < E_IN) {
        int s = is32 ? e32[e] : (int)e64[e];
        int d = is32 ? e32[E_IN + e] : (int)e64[E_IN + e];
        if (s != d) {
            int p = atomicAdd(&g_cursor[d], 1);
            g_csrc[p] = s;
        }
    }
    if (e < N_NODES) g_cnt[e] = 0;       // reset for next graph replay
}

// ---------------- W pre-split into mma B-fragment order -----------------------
// B fragment (m16n8k8 .col): lane l: b0 = W[k0 + l%4][n0 + l/4],
//                                     b1 = W[k0 + l%4 + 4][n0 + l/4].
// g_Wf[(ks*32 + ntg)*32 + lane] = (b0hi, b1hi, b0lo, b1lo) as float-bit tf32.
__global__ __launch_bounds__(256) void k_wsplit(const float* __restrict__ W) {
    int i = blockIdx.x * 256 + threadIdx.x;      // 0..8191
    int lane = i & 31, ntg = (i >> 5) & 31, ks = i >> 10;
    int t4 = lane & 3, g = lane >> 2;
    int col = ntg * 8 + g;
    float b0 = W[(ks * 8 + t4) * HC + col];
    float b1 = W[(ks * 8 + t4 + 4) * HC + col];
    unsigned b0h = tf32_rna(b0), b1h = tf32_rna(b1);
    unsigned b0l = tf32_rna(b0 - __uint_as_float(b0h));
    unsigned b1l = tf32_rna(b1 - __uint_as_float(b1h));
    g_Wf[i] = make_float4(__uint_as_float(b0h), __uint_as_float(b1h),
                          __uint_as_float(b0l), __uint_as_float(b1l));
}

// ---------------- projection GEMM (tensor cores, 3xTF32) + logits -------------
// Block: 256 threads = 8 warps = 2 row-groups x 4 col-groups.
// Warp tile: 32 rows x 64 cols = 2 m16 tiles x 8 n8 tiles; the 64-col slice is
// exactly one head -> logits close with a 4-lane quad reduction.
// D = Xhi*Whi + Xhi*Wlo + Xlo*Whi (fp32 accum): error ~1e-7.
__global__ __launch_bounds__(256, 2) void k_gemm(const float* __restrict__ x,
                                                 const float* __restrict__ attS,
                                                 const float* __restrict__ attD) {
    __shared__ float sAS[HC], sAD[HC];
    int t = threadIdx.x, warp = t >> 5, lane = t & 31;
    int g = lane >> 2, t4 = lane & 3;
    int mg = warp >> 2, ng = warp & 3;
    int rbase = blockIdx.x * 64 + mg * 32;

    if (t < HC) { sAS[t] = attS[t]; sAD[t] = attD[t]; }
    __syncthreads();

    float acc[2][8][4];
#pragma unroll
    for (int mt = 0; mt < 2; mt++)
#pragma unroll
        for (int nt = 0; nt < 8; nt++)
#pragma unroll
            for (int j = 0; j < 4; j++) acc[mt][nt][j] = 0.f;

#pragma unroll
    for (int ks = 0; ks < 8; ks++) {
        // A fragments for both m-tiles: load x, split hi/lo
        unsigned ah[2][4], al[2][4];
#pragma unroll
        for (int mt = 0; mt < 2; mt++) {
            const float* xp = x + (size_t)(rbase + mt * 16 + g) * F_DIM + ks * 8 + t4;
            float v0 = xp[0];            // (row g,    col t4)
            float v1 = xp[8 * F_DIM];    // (row g+8,  col t4)
            float v2 = xp[4];            // (row g,    col t4+4)
            float v3 = xp[8 * F_DIM + 4];
            ah[mt][0] = tf32_rna(v0); al[mt][0] = tf32_rna(v0 - __uint_as_float(ah[mt][0]));
            ah[mt][1] = tf32_rna(v1); al[mt][1] = tf32_rna(v1 - __uint_as_float(ah[mt][1]));
            ah[mt][2] = tf32_rna(v2); al[mt][2] = tf32_rna(v2 - __uint_as_float(ah[mt][2]));
            ah[mt][3] = tf32_rna(v3); al[mt][3] = tf32_rna(v3 - __uint_as_float(ah[mt][3]));
        }
#pragma unroll
        for (int nt = 0; nt < 8; nt++) {
            float4 b = g_Wf[((size_t)ks * 32 + ng * 8 + nt) * 32 + lane];  // LDG.128
            unsigned b0h = __float_as_uint(b.x), b1h = __float_as_uint(b.y);
            unsigned b0l = __float_as_uint(b.z), b1l = __float_as_uint(b.w);
#pragma unroll
            for (int mt = 0; mt < 2; mt++) {
                MMA_TF32(acc[mt][nt], ah[mt], b0h, b1h);
                MMA_TF32(acc[mt][nt], ah[mt], b0l, b1l);
                MMA_TF32(acc[mt][nt], al[mt], b0h, b1h);
            }
        }
    }

    // epilogue: logits (this warp's head = ng) + fp16 h store
    int head = ng, n0 = ng * 64;
    __half* hbase = (__half*)g_hv;
#pragma unroll
    for (int mt = 0; mt < 2; mt++) {
        int row0 = rbase + mt * 16 + g;          // and row0 + 8
        float as0 = 0.f, ad0 = 0.f, as1 = 0.f, ad1 = 0.f;
#pragma unroll
        for (int nt = 0; nt < 8; nt++) {
            int c = n0 + nt * 8 + 2 * t4;
            float* a = acc[mt][nt];
            as0 += a[0] * sAS[c] + a[1] * sAS[c + 1];
            ad0 += a[0] * sAD[c] + a[1] * sAD[c + 1];
            as1 += a[2] * sAS[c] + a[3] * sAS[c + 1];
            ad1 += a[2] * sAD[c] + a[3] * sAD[c + 1];
            *(__half2*)(hbase + (size_t)row0 * HC + c)       = __floats2half2_rn(a[0], a[1]);
            *(__half2*)(hbase + (size_t)(row0 + 8) * HC + c) = __floats2half2_rn(a[2], a[3]);
        }
        // quad reduce over t4 (lanes xor 1, 2)
        as0 += __shfl_xor_sync(0xffffffffu, as0, 1); as0 += __shfl_xor_sync(0xffffffffu, as0, 2);
        ad0 += __shfl_xor_sync(0xffffffffu, ad0, 1); ad0 += __shfl_xor_sync(0xffffffffu, ad0, 2);
        as1 += __shfl_xor_sync(0xffffffffu, as1, 1); as1 += __shfl_xor_sync(0xffffffffu, as1, 2);
        ad1 += __shfl_xor_sync(0xffffffffu, ad1, 1); ad1 += __shfl_xor_sync(0xffffffffu, ad1, 2);
        if (t4 == 0) {
            g_asrc[row0 * 4 + head] = as0;
            g_adst[row0 * 4 + head] = ad0;
            g_asrc[(row0 + 8) * 4 + head] = as1;
            g_adst[(row0 + 8) * 4 + head] = ad1;
        }
    }
}

// ---------------- softmax aggregation (single pass, one warp per (r, dst)) ----
// No max-shift: logits bounded far below 80, so exp(e) equals the reference's
// shifted softmax; den eps 1e-16 matches ref.
__global__ __launch_bounds__(256) void k_agg(const float* __restrict__ bias,
                                             float* __restrict__ out) {
    int gw = (blockIdx.x * blockDim.x + threadIdx.x) >> 5;
    int lane = threadIdx.x & 31;
    if (gw >= RN) return;
    int r = gw / N_NODES, i = gw - r * N_NODES;
    int head = lane >> 3;
    int start = g_rowptr[i], end = g_rowptr[i + 1];
    int rbase = r * N_NODES;

    float adsth = g_adst[(rbase + i) * 4 + head];

    float den = 1e-16f;
    float a0 = 0.f, a1 = 0.f, a2 = 0.f, a3 = 0.f;
    float a4 = 0.f, a5 = 0.f, a6 = 0.f, a7 = 0.f;

#pragma unroll 2
    for (int k = start; k < end; k++) {
        int s = g_csrc[k];
        float e = g_asrc[(rbase + s) * 4 + head] + adsth;
        e = (e > 0.f) ? e : 0.2f * e;
        float w = __expf(fminf(e, 80.f));
        den += w;
        uint4 u = g_hv[(size_t)(rbase + s) * 32 + lane];   // 16B/lane, 512B/warp
        float2 f0 = __half22float2(*reinterpret_cast<__half2*>(&u.x));
        float2 f1 = __half22float2(*reinterpret_cast<__half2*>(&u.y));
        float2 f2 = __half22float2(*reinterpret_cast<__half2*>(&u.z));
        float2 f3 = __half22float2(*reinterpret_cast<__half2*>(&u.w));
        a0 += w * f0.x; a1 += w * f0.y; a2 += w * f1.x; a3 += w * f1.y;
        a4 += w * f2.x; a5 += w * f2.y; a6 += w * f3.x; a7 += w * f3.y;
    }

    float inv = 1.0f / den;
    float a[8] = {a0 * inv, a1 * inv, a2 * inv, a3 * inv,
                  a4 * inv, a5 * inv, a6 * inv, a7 * inv};

    // head mean: lanes l, l^8, l^16, l^24 hold same channel, different heads
#pragma unroll
    for (int k = 0; k < 8; k++) {
        a[k] += __shfl_xor_sync(0xffffffffu, a[k], 8);
        a[k] += __shfl_xor_sync(0xffffffffu, a[k], 16);
    }

    if (lane < 8) {
        const float4* bp = (const float4*)bias;
        float4 b0 = bp[lane * 2], b1 = bp[lane * 2 + 1];
        float4 o0 = make_float4(0.25f * a[0] + b0.x, 0.25f * a[1] + b0.y,
                                0.25f * a[2] + b0.z, 0.25f * a[3] + b0.w);
        float4 o1 = make_float4(0.25f * a[4] + b1.x, 0.25f * a[5] + b1.y,
                                0.25f * a[6] + b1.z, 0.25f * a[7] + b1.w);
        float4* op = (float4*)(out + (size_t)(rbase + i) * 64 + lane * 8);
        op[0] = o0;
        op[1] = o1;
    }
}

// ---------------- launch ------------------------------------------------------
extern "C" void kernel_launch(void* const* d_in, const int* in_sizes, int n_in,
                              void* d_out, int out_size) {
    const float* x    = (const float*)d_in[0];
    const void*  ei   = d_in[1];
    const float* W    = (const float*)d_in[2];
    const float* attS = (const float*)d_in[3];
    const float* attD = (const float*)d_in[4];
    const float* bias = (const float*)d_in[5];
    float* out = (float*)d_out;

    k_count<<<(E_IN + 255) / 256, 256>>>(ei);
    k_wsplit<<<32, 256>>>(W);
    k_scan<<<1, 1024>>>();
    k_scatter<<<(E_IN + 255) / 256, 256>>>(ei);
    k_gemm<<<RN / 64, 256>>>(x, attS, attD);
    k_agg<<<RN / 8, 256>>>(bias, out);
}